// round 16
// baseline (speedup 1.0000x reference)
#include <cuda_runtime.h>
#include <cuda_fp16.h>
#include <math.h>
#include <stdint.h>

#define DD    160
#define QW    480      // 3*DD
#define NNODE 8192
#define PSZ   16
#define PNUM  512
#define MAXB  16

// ---------------- scratch (static device globals; no runtime allocation) ----
static __device__ float  g_rex [(size_t)MAXB*NNODE*DD];   // residual (fp32)
static __device__ float  g_orig[(size_t)MAXB*NNODE*DD];   // scatter target (fp32)
static __device__ __half g_ln  [(size_t)MAXB*NNODE*DD];   // LN outputs (fp16)
static __device__ __half g_tmp [(size_t)MAXB*NNODE*DD];   // attn outputs (fp16)
static __device__ __half g_qkv [(size_t)MAXB*NNODE*QW];   // qkv (fp16)
static __device__ __half g_wh  [921600];                  // fp16 weights, [n][k]

// ------------------------------------------------------------- helpers -----
__device__ __forceinline__ void mma16(float* c, const unsigned* a, const unsigned* b)
{
    asm volatile(
        "mma.sync.aligned.m16n8k16.row.col.f32.f16.f16.f32 "
        "{%0,%1,%2,%3}, {%4,%5,%6,%7}, {%8,%9}, {%0,%1,%2,%3};\n"
        : "+f"(c[0]), "+f"(c[1]), "+f"(c[2]), "+f"(c[3])
        : "r"(a[0]), "r"(a[1]), "r"(a[2]), "r"(a[3]), "r"(b[0]), "r"(b[1]));
}
__device__ __forceinline__ void ldsm4h(unsigned* r, const __half* p)
{
    unsigned a = (unsigned)__cvta_generic_to_shared(p);
    asm volatile("ldmatrix.sync.aligned.m8n8.x4.shared.b16 {%0,%1,%2,%3}, [%4];\n"
        : "=r"(r[0]), "=r"(r[1]), "=r"(r[2]), "=r"(r[3]) : "r"(a));
}
__device__ __forceinline__ void ldsm2h(unsigned* r, const __half* p)
{
    unsigned a = (unsigned)__cvta_generic_to_shared(p);
    asm volatile("ldmatrix.sync.aligned.m8n8.x2.shared.b16 {%0,%1}, [%2];\n"
        : "=r"(r[0]), "=r"(r[1]) : "r"(a));
}
__device__ __forceinline__ void ldsm2ht(unsigned* r, const __half* p)
{
    unsigned a = (unsigned)__cvta_generic_to_shared(p);
    asm volatile("ldmatrix.sync.aligned.m8n8.x2.trans.shared.b16 {%0,%1}, [%2];\n"
        : "=r"(r[0]), "=r"(r[1]) : "r"(a));
}
__device__ __forceinline__ unsigned pack_h2(float x, float y)
{
    __half2 h = __floats2half2_rn(x, y);
    return *(unsigned*)&h;
}

#define CP16(dst, src) \
    asm volatile("cp.async.cg.shared.global [%0], [%1], 16;\n" :: "r"(dst), "l"(src))
#define CP_COMMIT() asm volatile("cp.async.commit_group;\n")
#define CP_WAIT0()  asm volatile("cp.async.wait_group 0;\n")
#define CP_WAIT1()  asm volatile("cp.async.wait_group 1;\n")

// --------------------------------- weight prep: fp16 round + transpose -----
__global__ void prep_weights_kernel(const float* __restrict__ qs, const float* __restrict__ ps,
                                    const float* __restrict__ f1s, const float* __restrict__ f2s,
                                    const float* __restrict__ qn, const float* __restrict__ pn,
                                    const float* __restrict__ f1n, const float* __restrict__ f2n)
{
    int i = blockIdx.x*256 + threadIdx.x;
    if (i >= 921600) return;
    int j = i;
    const float* src; int N, segbase;
    if (j < 460800) {
        if      (j < 230400) { src = qs;  N = 480; segbase = 0; }
        else if (j < 307200) { src = ps;  N = 160; segbase = 230400; j -= 230400; }
        else if (j < 384000) { src = f1s; N = 160; segbase = 307200; j -= 307200; }
        else                 { src = f2s; N = 160; segbase = 384000; j -= 384000; }
    } else {
        j -= 460800;
        if      (j < 230400) { src = qn;  N = 480; segbase = 460800; }
        else if (j < 307200) { src = pn;  N = 160; segbase = 691200; j -= 230400; }
        else if (j < 384000) { src = f1n; N = 160; segbase = 768000; j -= 307200; }
        else                 { src = f2n; N = 160; segbase = 844800; j -= 384000; }
    }
    int lsz = 160*N;
    int l2 = j / lsz, rem = j - l2*lsz;
    int k = rem / N, n = rem - k*N;
    g_wh[segbase + l2*lsz + n*160 + k] = __float2half_rn(src[j]);
}

// --------------------------------------------------- embed + fused LN ------
__global__ void embed_kernel(const float* __restrict__ x, const int* __restrict__ te,
                             const int* __restrict__ reo_all,
                             const float* __restrict__ node_emb,
                             const float* __restrict__ tod_emb,
                             const float* __restrict__ dow_emb,
                             const float* __restrict__ in_w,
                             const float* __restrict__ in_b)
{
    int j = blockIdx.x, b = blockIdx.y, o = threadIdx.x;
    int lane = o & 31, wid = o >> 5;
    __shared__ float x1[12][3];
    __shared__ float red[5];
    int n = reo_all[j];
    if (o < 12) {
        int p = o;
        size_t base = ((size_t)(b*12 + p))*NNODE + n;
        x1[p][0] = x[base];
        x1[p][1] = (float)te[base*2 + 0] * (1.0f/288.0f);
        x1[p][2] = (float)te[base*2 + 1] * (1.0f/7.0f);
    }
    __syncthreads();
    float v;
    size_t tb = (((size_t)(b*12 + 11))*NNODE + n)*2;
    if (o < 64) {
        v = in_b[o];
        #pragma unroll
        for (int c = 0; c < 3; c++)
            #pragma unroll
            for (int p = 0; p < 12; p++)
                v += x1[p][c] * in_w[(c*12 + p)*64 + o];
    } else if (o < 96) {
        v = tod_emb[te[tb + 0]*32 + (o - 64)];
    } else if (o < 128) {
        v = dow_emb[te[tb + 1]*32 + (o - 96)];
    } else {
        v = node_emb[(size_t)n*32 + (o - 128)];
    }
    float s = v;
    #pragma unroll
    for (int m = 16; m; m >>= 1) s += __shfl_xor_sync(0xffffffffu, s, m);
    if (lane == 0) red[wid] = s;
    __syncthreads();
    float mean = (red[0] + red[1] + red[2] + red[3] + red[4]) * (1.0f/160.0f);
    float d = v - mean;
    float q = d*d;
    #pragma unroll
    for (int m = 16; m; m >>= 1) q += __shfl_xor_sync(0xffffffffu, q, m);
    __syncthreads();
    if (lane == 0) red[wid] = q;
    __syncthreads();
    float w = rsqrtf((red[0] + red[1] + red[2] + red[3] + red[4]) * (1.0f/160.0f) + 1e-6f);
    size_t row = ((size_t)b*NNODE + j)*DD + o;
    g_rex[row] = v;
    g_ln[row] = __float2half_rn(d*w);
}

// ------------------------------------------------------------------ gemm ----
// 64-row block, FULL K resident in smem (no K pipeline), 3 CTAs/SM.
// A: fp16 [row][k]. Wt: fp16 [n][k] stride 160.
// OP: 1 = bias+residual -> fp32 C (+opt fused LN -> fp16); 3 = bias -> fp16
template<int OP, int LNOUT>
__global__ void __launch_bounds__(256, 3) gemm_mma_kernel(
    const __half* __restrict__ A, const __half* __restrict__ Wt,
    const float* __restrict__ bias, const float* __restrict__ Rsd,
    float* __restrict__ Cf, __half* __restrict__ Ch,
    __half* __restrict__ LnOut, int ldc)
{
    extern __shared__ char smraw[];
    __half* As = (__half*)smraw;       // [64][168]
    __half* Bs = As + 64*168;          // [160][168]
    float*  S  = (float*)smraw;        // [64][164] (epilogue reuse, LNOUT)
    const int tid = threadIdx.x, lane = tid & 31, wid = tid >> 5;
    const int warp_m = wid >> 2, warp_n = wid & 3;
    const int row0 = blockIdx.x*64, colbase = blockIdx.y*160;

    const int lrow = (lane & 7) + ((lane >> 3) & 1)*8;
    const int lkof = ((lane >> 4) & 1)*8;

    unsigned sAs = (unsigned)__cvta_generic_to_shared(As);
    unsigned sBs = (unsigned)__cvta_generic_to_shared(Bs);

    // one-shot loads: A = 64x20 chunks, W = 160x20 chunks
    {
        const __half* Ab = A + (size_t)row0*DD;
        #pragma unroll
        for (int i = 0; i < 5; i++) {
            int idx = tid + i*256; int r = idx/20, c = idx%20;
            CP16(sAs + (unsigned)((r*168 + c*8)*2), Ab + (size_t)r*DD + c*8);
        }
        const __half* Wb = Wt + (size_t)colbase*160;
        #pragma unroll
        for (int i = 0; i < 13; i++) {
            int idx = tid + i*256;
            if (idx < 3200) {
                int n = idx/20, c = idx%20;
                CP16(sBs + (unsigned)((n*168 + c*8)*2), Wb + (size_t)n*160 + c*8);
            }
        }
    }
    CP_COMMIT(); CP_WAIT0();
    __syncthreads();

    float acc[2][5][4] = {};
    #pragma unroll
    for (int ks = 0; ks < 10; ks++) {
        unsigned af[2][4], bf[5][2];
        #pragma unroll
        for (int i = 0; i < 2; i++)
            ldsm4h(af[i], As + (warp_m*32 + i*16 + lrow)*168 + ks*16 + lkof);
        #pragma unroll
        for (int j = 0; j < 5; j++)
            ldsm2h(bf[j], Bs + (warp_n*40 + j*8 + (lane & 7))*168
                          + ks*16 + ((lane >> 3) & 1)*8);
        #pragma unroll
        for (int i = 0; i < 2; i++)
            #pragma unroll
            for (int j = 0; j < 5; j++)
                mma16(acc[i][j], af[i], bf[j]);
    }

    if (LNOUT) __syncthreads();        // about to overwrite As/Bs with S

    int rwl = warp_m*32 + (lane >> 2);
    int cwl = warp_n*40 + 2*(lane & 3);
    #pragma unroll
    for (int j = 0; j < 5; j++) {
        int cl = cwl + j*8, c = colbase + cl;
        float b0 = bias[c], b1 = bias[c + 1];
        #pragma unroll
        for (int i = 0; i < 2; i++) {
            #pragma unroll
            for (int h = 0; h < 2; h++) {
                int rl = rwl + i*16 + h*8, r = row0 + rl;
                float v0 = acc[i][j][2*h + 0] + b0;
                float v1 = acc[i][j][2*h + 1] + b1;
                if (OP == 1) {
                    float2 rs = *(const float2*)(Rsd + (size_t)r*ldc + c);
                    v0 += rs.x; v1 += rs.y;
                    *(float2*)(Cf + (size_t)r*ldc + c) = make_float2(v0, v1);
                    if (LNOUT) { S[rl*164 + cl] = v0; S[rl*164 + cl + 1] = v1; }
                }
                if (OP == 3)
                    *(__half2*)(Ch + (size_t)r*ldc + c) = __floats2half2_rn(v0, v1);
            }
        }
    }

    if (LNOUT) {
        __syncthreads();
        // 8 warps x 8 rows: full LN per row
        #pragma unroll 1
        for (int rr = 0; rr < 8; rr++) {
            int rl = wid*8 + rr;
            float vv[5]; float s = 0.f;
            #pragma unroll
            for (int q = 0; q < 5; q++) { vv[q] = S[rl*164 + lane + 32*q]; s += vv[q]; }
            #pragma unroll
            for (int m = 16; m; m >>= 1) s += __shfl_xor_sync(0xffffffffu, s, m);
            float mean = s * (1.0f/160.0f);
            float qv = 0.f;
            #pragma unroll
            for (int q = 0; q < 5; q++) { float d = vv[q]-mean; qv += d*d; }
            #pragma unroll
            for (int m = 16; m; m >>= 1) qv += __shfl_xor_sync(0xffffffffu, qv, m);
            float w = rsqrtf(qv * (1.0f/160.0f) + 1e-6f);
            __half* yr = LnOut + (size_t)(row0 + rl)*DD;
            #pragma unroll
            for (int q = 0; q < 5; q++)
                yr[lane + 32*q] = __float2half_rn((vv[q]-mean)*w);
        }
    }
}

// ------------------------------------------------------------- fused MLP ----
template<int LNOUT>
__global__ void __launch_bounds__(256, 2) mlp_mma_kernel(
    const __half* __restrict__ A, const __half* __restrict__ W1,
    const float* __restrict__ b1, const __half* __restrict__ W2,
    const float* __restrict__ b2, const float* __restrict__ Rsd,
    float* __restrict__ Cf, __half* __restrict__ LnOut)
{
    extern __shared__ char smraw[];
    __half* As = (__half*)smraw;       // [3][128][40]
    __half* Bs = As + 3*128*40;        // [3][160][40]
    __half* Hs = Bs + 3*160*40;        // [128][168]
    float*  S  = (float*)smraw;        // [128][164] (epilogue reuse, LNOUT)
    const int tid = threadIdx.x, lane = tid & 31, wid = tid >> 5;
    const int warp_m = wid >> 2, warp_n = wid & 3;
    const int row0 = blockIdx.x*128;

    const int lrow = (lane & 7) + ((lane >> 3) & 1)*8;
    const int lkof = ((lane >> 4) & 1)*8;

    unsigned sAs = (unsigned)__cvta_generic_to_shared(As);
    unsigned sBs = (unsigned)__cvta_generic_to_shared(Bs);

    float acc[4][5][4] = {};

    auto load_tile = [&](int k0, int buf) {
        const __half* Ab = A + (size_t)row0*DD + k0;
        #pragma unroll
        for (int i = 0; i < 2; i++) {
            int idx = tid + i*256; int r = idx >> 2, c = idx & 3;
            CP16(sAs + (unsigned)((buf*128*40 + r*40 + c*8)*2),
                 Ab + (size_t)r*DD + c*8);
        }
        const __half* Wb = W1 + k0;
        #pragma unroll
        for (int i = 0; i < 3; i++) {
            int idx = tid + i*256;
            if (idx < 640) {
                int n = idx >> 2, c = idx & 3;
                CP16(sBs + (unsigned)((buf*160*40 + n*40 + c*8)*2),
                     Wb + (size_t)n*160 + c*8);
            }
        }
    };
    auto load_w2 = [&](int k0, int buf) {
        const __half* Wb = W2 + k0;
        #pragma unroll
        for (int i = 0; i < 3; i++) {
            int idx = tid + i*256;
            if (idx < 640) {
                int n = idx >> 2, c = idx & 3;
                CP16(sBs + (unsigned)((buf*160*40 + n*40 + c*8)*2),
                     Wb + (size_t)n*160 + c*8);
            }
        }
    };

    // pass 1 : H = gelu(A@W1 + b1)
    load_tile(0, 0);  CP_COMMIT();
    load_tile(32, 1); CP_COMMIT();
    for (int t = 0; t < 5; t++) {
        if (t < 4) CP_WAIT1(); else CP_WAIT0();
        __syncthreads();
        if (t < 3) { load_tile((t + 2)*32, (t + 2)%3); CP_COMMIT(); }
        int bsel = t % 3;
        const __half* Ab = As + bsel*128*40;
        const __half* Bb = Bs + bsel*160*40;
        #pragma unroll
        for (int ks = 0; ks < 2; ks++) {
            unsigned af[4][4], bf[5][2];
            #pragma unroll
            for (int i = 0; i < 4; i++)
                ldsm4h(af[i], Ab + (warp_m*64 + i*16 + lrow)*40 + ks*16 + lkof);
            #pragma unroll
            for (int j = 0; j < 5; j++)
                ldsm2h(bf[j], Bb + (warp_n*40 + j*8 + (lane & 7))*40
                              + ks*16 + ((lane >> 3) & 1)*8);
            #pragma unroll
            for (int i = 0; i < 4; i++)
                #pragma unroll
                for (int j = 0; j < 5; j++)
                    mma16(acc[i][j], af[i], bf[j]);
        }
    }
    __syncthreads();

    const int rwl = warp_m*64 + (lane >> 2);
    const int cwl = warp_n*40 + 2*(lane & 3);
    #pragma unroll
    for (int j = 0; j < 5; j++) {
        int cl = cwl + j*8;
        float b0 = b1[cl], b1v = b1[cl + 1];
        #pragma unroll
        for (int i = 0; i < 4; i++) {
            #pragma unroll
            for (int h = 0; h < 2; h++) {
                int rl = rwl + i*16 + h*8;
                float v0 = acc[i][j][2*h + 0] + b0;
                float v1 = acc[i][j][2*h + 1] + b1v;
                v0 = 0.5f*v0*(1.0f + erff(v0*0.70710678118654752f));
                v1 = 0.5f*v1*(1.0f + erff(v1*0.70710678118654752f));
                *(__half2*)(Hs + rl*168 + cl) = __floats2half2_rn(v0, v1);
                acc[i][j][2*h] = 0.f; acc[i][j][2*h + 1] = 0.f;
            }
        }
    }
    __syncthreads();

    // pass 2 : C = H@W2 + b2 + Rsd
    load_w2(0, 0);  CP_COMMIT();
    load_w2(32, 1); CP_COMMIT();
    for (int t = 0; t < 5; t++) {
        if (t < 4) CP_WAIT1(); else CP_WAIT0();
        __syncthreads();
        if (t < 3) { load_w2((t + 2)*32, (t + 2)%3); CP_COMMIT(); }
        int bsel = t % 3;
        const __half* Bb = Bs + bsel*160*40;
        #pragma unroll
        for (int ks = 0; ks < 2; ks++) {
            unsigned af[4][4], bf[5][2];
            #pragma unroll
            for (int i = 0; i < 4; i++)
                ldsm4h(af[i], Hs + (warp_m*64 + i*16 + lrow)*168
                              + t*32 + ks*16 + lkof);
            #pragma unroll
            for (int j = 0; j < 5; j++)
                ldsm2h(bf[j], Bb + (warp_n*40 + j*8 + (lane & 7))*40
                              + ks*16 + ((lane >> 3) & 1)*8);
            #pragma unroll
            for (int i = 0; i < 4; i++)
                #pragma unroll
                for (int j = 0; j < 5; j++)
                    mma16(acc[i][j], af[i], bf[j]);
        }
    }
    __syncthreads();

    #pragma unroll
    for (int j = 0; j < 5; j++) {
        int cl = cwl + j*8;
        float b0 = b2[cl], b1v = b2[cl + 1];
        #pragma unroll
        for (int i = 0; i < 4; i++) {
            #pragma unroll
            for (int h = 0; h < 2; h++) {
                int rl = rwl + i*16 + h*8, r = row0 + rl;
                float2 rs = *(const float2*)(Rsd + (size_t)r*DD + cl);
                float v0 = acc[i][j][2*h + 0] + b0 + rs.x;
                float v1 = acc[i][j][2*h + 1] + b1v + rs.y;
                *(float2*)(Cf + (size_t)r*DD + cl) = make_float2(v0, v1);
                if (LNOUT) { S[rl*164 + cl] = v0; S[rl*164 + cl + 1] = v1; }
            }
        }
    }

    if (LNOUT) {
        __syncthreads();
        #pragma unroll 1
        for (int rr = 0; rr < 16; rr++) {
            int rl = wid*16 + rr;
            float vv[5]; float s = 0.f;
            #pragma unroll
            for (int q = 0; q < 5; q++) { vv[q] = S[rl*164 + lane + 32*q]; s += vv[q]; }
            #pragma unroll
            for (int m = 16; m; m >>= 1) s += __shfl_xor_sync(0xffffffffu, s, m);
            float mean = s * (1.0f/160.0f);
            float qv = 0.f;
            #pragma unroll
            for (int q = 0; q < 5; q++) { float d = vv[q]-mean; qv += d*d; }
            #pragma unroll
            for (int m = 16; m; m >>= 1) qv += __shfl_xor_sync(0xffffffffu, qv, m);
            float w = rsqrtf(qv * (1.0f/160.0f) + 1e-6f);
            __half* yr = LnOut + (size_t)(row0 + rl)*DD;
            #pragma unroll
            for (int q = 0; q < 5; q++)
                yr[lane + 32*q] = __float2half_rn((vv[q]-mean)*w);
        }
    }
}

// ------------------------------------------------------ spatial attention ----
__global__ void __launch_bounds__(128) spat_attn_kernel(const __half* __restrict__ qkv,
                                                        __half* __restrict__ out)
{
    extern __shared__ __half G[];          // [4][16][488]
    const int tid = threadIdx.x, lane = tid & 31, w = tid >> 5;
    const int gbase = blockIdx.x*4;
    unsigned sG = (unsigned)__cvta_generic_to_shared(G);

    #pragma unroll
    for (int i = 0; i < 30; i++) {
        int idx = tid + i*128;
        int grp = idx/960, rem = idx - grp*960;
        int row = rem/60, c = rem - row*60;
        CP16(sG + (unsigned)(((grp*16 + row)*488 + c*8)*2),
             qkv + ((size_t)(gbase + grp)*16 + row)*QW + c*8);
    }
    CP_COMMIT(); CP_WAIT0();
    __syncthreads();

    const __half* Gm = G + w*16*488;
    const int lrow = (lane & 7) + ((lane >> 3) & 1)*8;
    const int lkof = ((lane >> 4) & 1)*8;
    const float scale = 0.07905694150420949f;

    float sv0[4] = {}, sv1[4] = {};
    #pragma unroll
    for (int ks = 0; ks < 10; ks++) {
        unsigned af[4], bf0[2], bf1[2];
        ldsm4h(af, Gm + lrow*488 + ks*16 + lkof);
        ldsm2h(bf0, Gm + ((lane & 7)    )*488 + 160 + ks*16 + ((lane >> 3) & 1)*8);
        ldsm2h(bf1, Gm + ((lane & 7) + 8)*488 + 160 + ks*16 + ((lane >> 3) & 1)*8);
        mma16(sv0, af, bf0);
        mma16(sv1, af, bf1);
    }

    float st[4] = {sv0[0]*scale, sv0[1]*scale, sv1[0]*scale, sv1[1]*scale};
    float sb[4] = {sv0[2]*scale, sv0[3]*scale, sv1[2]*scale, sv1[3]*scale};
    float mt = fmaxf(fmaxf(st[0], st[1]), fmaxf(st[2], st[3]));
    float mb = fmaxf(fmaxf(sb[0], sb[1]), fmaxf(sb[2], sb[3]));
    mt = fmaxf(mt, __shfl_xor_sync(0xffffffffu, mt, 1));
    mt = fmaxf(mt, __shfl_xor_sync(0xffffffffu, mt, 2));
    mb = fmaxf(mb, __shfl_xor_sync(0xffffffffu, mb, 1));
    mb = fmaxf(mb, __shfl_xor_sync(0xffffffffu, mb, 2));
    float pt[4], pb[4], sumt = 0.f, sumb = 0.f;
    #pragma unroll
    for (int q = 0; q < 4; q++) {
        pt[q] = expf(st[q] - mt); sumt += pt[q];
        pb[q] = expf(sb[q] - mb); sumb += pb[q];
    }
    sumt += __shfl_xor_sync(0xffffffffu, sumt, 1);
    sumt += __shfl_xor_sync(0xffffffffu, sumt, 2);
    sumb += __shfl_xor_sync(0xffffffffu, sumb, 1);
    sumb += __shfl_xor_sync(0xffffffffu, sumb, 2);
    float it = 1.0f/sumt, ib = 1.0f/sumb;

    unsigned pa[4];
    pa[0] = pack_h2(pt[0]*it, pt[1]*it);
    pa[1] = pack_h2(pb[0]*ib, pb[1]*ib);
    pa[2] = pack_h2(pt[2]*it, pt[3]*it);
    pa[3] = pack_h2(pb[2]*ib, pb[3]*ib);

    int r = lane >> 2, c2 = 2*(lane & 3);
    size_t orow_t = ((size_t)(gbase + w)*16 + r    )*DD;
    size_t orow_b = ((size_t)(gbase + w)*16 + r + 8)*DD;
    #pragma unroll
    for (int j = 0; j < 20; j++) {
        unsigned bf[2];
        ldsm2ht(bf, Gm + ((lane & 7) + ((lane >> 3) & 1)*8)*488 + 320 + j*8);
        float o4[4] = {};
        mma16(o4, pa, bf);
        *(__half2*)(out + orow_t + j*8 + c2) = __floats2half2_rn(o4[0], o4[1]);
        *(__half2*)(out + orow_b + j*8 + c2) = __floats2half2_rn(o4[2], o4[3]);
    }
}

// --------------------------------------------------------- node attention ----
__global__ void __launch_bounds__(256, 2) node_attn_kernel(const __half* __restrict__ qkv,
                                                           __half* __restrict__ out)
{
    extern __shared__ char smraw[];
    __half* Qs   = (__half*)smraw;          // [64][168]
    __half* Ks   = Qs + 64*168;             // [2][64][168]
    __half* Vs   = Ks + 2*64*168;           // [64][168]
    __half* Ps16 = Vs + 64*168;             // [64][72]
    float*  l_s  = (float*)(Ps16 + 64*72);  // [64]

    const int qt = blockIdx.x, g = blockIdx.y;
    const int b = g >> 4, s = g & 15;
    const int tid = threadIdx.x, lane = tid & 31, w = tid >> 5;
    const int wm = w >> 2, wn = w & 3;
    const int ar = wm*32 + (lane >> 2);
    const int lrow = (lane & 7) + ((lane >> 3) & 1)*8;
    const int lkof = ((lane >> 4) & 1)*8;
    const size_t rowstride = (size_t)PSZ*QW;
    const __half* base = qkv + (size_t)b*NNODE*QW + (size_t)s*QW;
    const float scale = 0.07905694150420949f;

    unsigned sQ = (unsigned)__cvta_generic_to_shared(Qs);
    unsigned sK = (unsigned)__cvta_generic_to_shared(Ks);
    unsigned sV = (unsigned)__cvta_generic_to_shared(Vs);

    if (tid < 64) l_s[tid] = 0.f;

    auto ldK = [&](int kt, int buf) {
        #pragma unroll
        for (int i = 0; i < 5; i++) {
            int idx = tid + i*256; int r = idx/20, c = idx%20;
            CP16(sK + (unsigned)((buf*64*168 + r*168 + c*8)*2),
                 base + (size_t)(kt*64 + r)*rowstride + 160 + c*8);
        }
    };
    auto ldV = [&](int kt) {
        #pragma unroll
        for (int i = 0; i < 5; i++) {
            int idx = tid + i*256; int r = idx/20, c = idx%20;
            CP16(sV + (unsigned)((r*168 + c*8)*2),
                 base + (size_t)(kt*64 + r)*rowstride + 320 + c*8);
        }
    };
    #pragma unroll
    for (int i = 0; i < 5; i++) {
        int idx = tid + i*256; int r = idx/20, c = idx%20;
        CP16(sQ + (unsigned)((r*168 + c*8)*2),
             base + (size_t)(qt*64 + r)*rowstride + c*8);
    }
    ldK(0, 0);
    CP_COMMIT();

    float o[2][5][4] = {};

    for (int kt = 0; kt < 8; kt++) {
        CP_WAIT0();
        __syncthreads();
        ldV(kt); CP_COMMIT();
        if (kt < 7) ldK(kt + 1, (kt + 1) & 1);
        CP_COMMIT();
        const __half* Kb = Ks + (kt & 1)*64*168;

        float sv[2][2][4] = {};
        #pragma unroll
        for (int ks = 0; ks < 10; ks++) {
            unsigned af0[4], af1[4], bf0[2], bf1[2];
            ldsm4h(af0, Qs + (wm*32      + lrow)*168 + ks*16 + lkof);
            ldsm4h(af1, Qs + (wm*32 + 16 + lrow)*168 + ks*16 + lkof);
            ldsm2h(bf0, Kb + (wn*16     + (lane & 7))*168 + ks*16 + ((lane >> 3) & 1)*8);
            ldsm2h(bf1, Kb + (wn*16 + 8 + (lane & 7))*168 + ks*16 + ((lane >> 3) & 1)*8);
            mma16(sv[0][0], af0, bf0); mma16(sv[0][1], af0, bf1);
            mma16(sv[1][0], af1, bf0); mma16(sv[1][1], af1, bf1);
        }

        #pragma unroll
        for (int i = 0; i < 2; i++) {
            int r0 = ar + 16*i;
            float e[2][4];
            #pragma unroll
            for (int j = 0; j < 2; j++)
                #pragma unroll
                for (int q = 0; q < 4; q++)
                    e[j][q] = __expf(sv[i][j][q]*scale);
            #pragma unroll
            for (int j = 0; j < 2; j++) {
                int c0 = wn*16 + 8*j + 2*(lane & 3);
                *(__half2*)&Ps16[(r0    )*72 + c0] = __floats2half2_rn(e[j][0], e[j][1]);
                *(__half2*)&Ps16[(r0 + 8)*72 + c0] = __floats2half2_rn(e[j][2], e[j][3]);
            }
            float rs0 = e[0][0] + e[0][1] + e[1][0] + e[1][1];
            float rs8 = e[0][2] + e[0][3] + e[1][2] + e[1][3];
            rs0 += __shfl_xor_sync(0xffffffffu, rs0, 1);
            rs0 += __shfl_xor_sync(0xffffffffu, rs0, 2);
            rs8 += __shfl_xor_sync(0xffffffffu, rs8, 1);
            rs8 += __shfl_xor_sync(0xffffffffu, rs8, 2);
            if ((lane & 3) == 0) {
                atomicAdd(&l_s[r0], rs0);
                atomicAdd(&l_s[r0 + 8], rs8);
            }
        }
        __syncthreads();

        CP_WAIT1();

        #pragma unroll
        for (int ks = 0; ks < 4; ks++) {
            unsigned af0[4], af1[4], bf[5][2];
            ldsm4h(af0, Ps16 + (wm*32      + lrow)*72 + ks*16 + lkof);
            ldsm4h(af1, Ps16 + (wm*32 + 16 + lrow)*72 + ks*16 + lkof);
            #pragma unroll
            for (int j = 0; j < 5; j++)
                ldsm2ht(bf[j], Vs + (ks*16 + (lane & 7) + ((lane >> 3) & 1)*8)*168
                               + wn*40 + j*8);
            #pragma unroll
            for (int j = 0; j < 5; j++) { mma16(o[0][j], af0, bf[j]); mma16(o[1][j], af1, bf[j]); }
        }
    }

    __syncthreads();
    #pragma unroll
    for (int i = 0; i < 2; i++)
        #pragma unroll
        for (int h = 0; h < 2; h++) {
            int rl = ar + 16*i + 8*h;
            float inv = 1.0f / l_s[rl];
            size_t orow = ((size_t)b*NNODE + (size_t)(qt*64 + rl)*PSZ + s)*DD;
            #pragma unroll
            for (int j = 0; j < 5; j++) {
                int c = wn*40 + j*8 + 2*(lane & 3);
                *(__half2*)(out + orow + c) =
                    __floats2half2_rn(o[i][j][2*h]*inv, o[i][j][2*h + 1]*inv);
            }
        }
}

// --------------------------------------------------- scatter / regression ----
__global__ void zero_kernel(float* p, size_t n)
{
    size_t i = (size_t)blockIdx.x*blockDim.x + threadIdx.x;
    if (i < n) p[i] = 0.f;
}

__global__ void scatter_kernel(const float* __restrict__ rex, float* __restrict__ orig,
                               const int* __restrict__ ori, const int* __restrict__ reo)
{
    int i = blockIdx.x, b = blockIdx.y, d = threadIdx.x;
    orig[((size_t)b*NNODE + ori[i])*DD + d] = rex[((size_t)b*NNODE + reo[i])*DD + d];
}

__global__ void __launch_bounds__(256) pred_kernel(const float* __restrict__ orig,
                                                   const float* __restrict__ reg_w,
                                                   const float* __restrict__ reg_b,
                                                   float* __restrict__ out)
{
    __shared__ float T[32][164];
    __shared__ float Wsh[12*160];
    int n0 = blockIdx.x*32, b = blockIdx.y, tid = threadIdx.x;
    for (int t = tid; t < 12*160; t += 256) Wsh[t] = reg_w[t];
    for (int t = tid; t < 32*160; t += 256)
        T[t/160][t%160] = orig[((size_t)b*NNODE + n0 + t/160)*DD + t%160];
    __syncthreads();
    for (int t = tid; t < 384; t += 256) {
        int o = t/32, nn = t%32;
        float acc = reg_b[o];
        #pragma unroll 8
        for (int d = 0; d < 160; d++) acc += Wsh[o*160 + d]*T[nn][d];
        out[((size_t)(b*12 + o))*NNODE + n0 + nn] = acc;
    }
}

// ---------------------------------------------------------------- launch ----
extern "C" void kernel_launch(void* const* d_in, const int* in_sizes, int n_in,
                              void* d_out, int out_size)
{
    const float* x        = (const float*)d_in[0];
    const int*   te       = (const int*)  d_in[1];
    const int*   reo_all  = (const int*)  d_in[2];
    const int*   ori_p    = (const int*)  d_in[3];
    const int*   reo_p    = (const int*)  d_in[4];
    const float* node_emb = (const float*)d_in[5];
    const float* tod_emb  = (const float*)d_in[6];
    const float* dow_emb  = (const float*)d_in[7];
    const float* in_w     = (const float*)d_in[8];
    const float* in_b     = (const float*)d_in[9];
    const float* qkv_s_w  = (const float*)d_in[10];
    const float* qkv_s_b  = (const float*)d_in[11];
    const float* proj_s_w = (const float*)d_in[12];
    const float* proj_s_b = (const float*)d_in[13];
    const float* fc1_s_w  = (const float*)d_in[14];
    const float* fc1_s_b  = (const float*)d_in[15];
    const float* fc2_s_w  = (const float*)d_in[16];
    const float* fc2_s_b  = (const float*)d_in[17];
    const float* qkv_n_w  = (const float*)d_in[18];
    const float* qkv_n_b  = (const float*)d_in[19];
    const float* proj_n_w = (const float*)d_in[20];
    const float* proj_n_b = (const float*)d_in[21];
    const float* fc1_n_w  = (const float*)d_in[22];
    const float* fc1_n_b  = (const float*)d_in[23];
    const float* fc2_n_w  = (const float*)d_in[24];
    const float* fc2_n_b  = (const float*)d_in[25];
    const float* reg_w    = (const float*)d_in[26];
    const float* reg_b    = (const float*)d_in[27];
    float* out = (float*)d_out;

    int B = in_sizes[0] / (12*NNODE);
    int M = B*NNODE;

    float *rex, *orig;
    __half *ln, *tmp, *qkv, *wh;
    cudaGetSymbolAddress((void**)&rex,  g_rex);
    cudaGetSymbolAddress((void**)&orig, g_orig);
    cudaGetSymbolAddress((void**)&ln,   g_ln);
    cudaGetSymbolAddress((void**)&tmp,  g_tmp);
    cudaGetSymbolAddress((void**)&qkv,  g_qkv);
    cudaGetSymbolAddress((void**)&wh,   g_wh);

    const int GEMM_SMEM = (64 + 160)*168*2;                            // 75264 -> 3 CTAs/SM
    const int MLP_SMEM  = (3*128*40 + 3*160*40 + 128*168)*2;           // 112128
    const int ATTN_SMEM = (64*168*4)*2 + 64*72*2 + 64*4;               // 95488
    const int SPAT_SMEM = 4*16*488*2;                                  // 62464
    cudaFuncSetAttribute(gemm_mma_kernel<1,1>, cudaFuncAttributeMaxDynamicSharedMemorySize, GEMM_SMEM);
    cudaFuncSetAttribute(gemm_mma_kernel<1,0>, cudaFuncAttributeMaxDynamicSharedMemorySize, GEMM_SMEM);
    cudaFuncSetAttribute(gemm_mma_kernel<3,0>, cudaFuncAttributeMaxDynamicSharedMemorySize, GEMM_SMEM);
    cudaFuncSetAttribute(mlp_mma_kernel<1>,    cudaFuncAttributeMaxDynamicSharedMemorySize, MLP_SMEM);
    cudaFuncSetAttribute(mlp_mma_kernel<0>,    cudaFuncAttributeMaxDynamicSharedMemorySize, MLP_SMEM);
    cudaFuncSetAttribute(node_attn_kernel,     cudaFuncAttributeMaxDynamicSharedMemorySize, ATTN_SMEM);
    cudaFuncSetAttribute(spat_attn_kernel,     cudaFuncAttributeMaxDynamicSharedMemorySize, SPAT_SMEM);

    prep_weights_kernel<<<3600, 256>>>(qkv_s_w, proj_s_w, fc1_s_w, fc2_s_w,
                                       qkv_n_w, proj_n_w, fc1_n_w, fc2_n_w);

    embed_kernel<<<dim3(NNODE, B), DD>>>(x, te, reo_all, node_emb, tod_emb, dow_emb,
                                         in_w, in_b);

    for (int l = 0; l < 3; l++) {
        const __half* Wq_s = wh + 0      + (size_t)l*76800;
        const __half* Wp_s = wh + 230400 + (size_t)l*25600;
        const __half* W1_s = wh + 307200 + (size_t)l*25600;
        const __half* W2_s = wh + 384000 + (size_t)l*25600;
        const __half* Wq_n = wh + 460800 + (size_t)l*76800;
        const __half* Wp_n = wh + 691200 + (size_t)l*25600;
        const __half* W1_n = wh + 768000 + (size_t)l*25600;
        const __half* W2_n = wh + 844800 + (size_t)l*25600;
        size_t ob3 = (size_t)l*QW, ob1 = (size_t)l*DD;

        // --- spatial attention block ---
        gemm_mma_kernel<3,0><<<dim3(M/64, 3), 256, GEMM_SMEM>>>(ln, Wq_s, qkv_s_b + ob3,
                                                nullptr, nullptr, qkv, nullptr, QW);
        spat_attn_kernel<<<M/64, 128, SPAT_SMEM>>>(qkv, tmp);
        gemm_mma_kernel<1,1><<<dim3(M/64, 1), 256, GEMM_SMEM>>>(tmp, Wp_s, proj_s_b + ob1,
                                                rex, rex, nullptr, ln, DD);
        // --- spatial MLP (fused) ---
        mlp_mma_kernel<1><<<M/128, 256, MLP_SMEM>>>(ln, W1_s, fc1_s_b + ob1,
                                                W2_s, fc2_s_b + ob1, rex, rex, ln);
        // --- node attention block ---
        gemm_mma_kernel<3,0><<<dim3(M/64, 3), 256, GEMM_SMEM>>>(ln, Wq_n, qkv_n_b + ob3,
                                                nullptr, nullptr, qkv, nullptr, QW);
        node_attn_kernel<<<dim3(PNUM/64, B*PSZ), 256, ATTN_SMEM>>>(qkv, tmp);
        gemm_mma_kernel<1,1><<<dim3(M/64, 1), 256, GEMM_SMEM>>>(tmp, Wp_n, proj_n_b + ob1,
                                                rex, rex, nullptr, ln, DD);
        // --- node MLP (fused) ---
        if (l < 2)
            mlp_mma_kernel<1><<<M/128, 256, MLP_SMEM>>>(ln, W1_n, fc1_n_b + ob1,
                                                W2_n, fc2_n_b + ob1, rex, rex, ln);
        else
            mlp_mma_kernel<0><<<M/128, 256, MLP_SMEM>>>(ln, W1_n, fc1_n_b + ob1,
                                                W2_n, fc2_n_b + ob1, rex, rex, nullptr);
    }

    size_t tot = (size_t)M*DD;
    zero_kernel<<<(unsigned)((tot + 255)/256), 256>>>(orig, tot);
    scatter_kernel<<<dim3(NNODE, B), DD>>>(rex, orig, ori_p, reo_p);
    pred_kernel<<<dim3(NNODE/32, B), 256>>>(orig, reg_w, reg_b, out);
}

// round 17
// speedup vs baseline: 1.1568x; 1.1568x over previous
#include <cuda_runtime.h>
#include <cuda_fp16.h>
#include <math.h>
#include <stdint.h>

#define DD    160
#define QW    480      // 3*DD
#define NNODE 8192
#define PSZ   16
#define PNUM  512
#define MAXB  16

// ---------------- scratch (static device globals; no runtime allocation) ----
static __device__ float  g_rex [(size_t)MAXB*NNODE*DD];   // residual (fp32)
static __device__ __half g_ln  [(size_t)MAXB*NNODE*DD];   // LN outputs (fp16)
static __device__ __half g_tmp [(size_t)MAXB*NNODE*DD];   // attn outputs (fp16)
static __device__ __half g_qkv [(size_t)MAXB*NNODE*QW];   // qkv (fp16)
static __device__ __half g_wh  [921600];                  // fp16 weights, [n][k]
static __device__ int    g_map [NNODE];                   // ori -> reo inverse map

// ------------------------------------------------------------- helpers -----
__device__ __forceinline__ void mma16(float* c, const unsigned* a, const unsigned* b)
{
    asm volatile(
        "mma.sync.aligned.m16n8k16.row.col.f32.f16.f16.f32 "
        "{%0,%1,%2,%3}, {%4,%5,%6,%7}, {%8,%9}, {%0,%1,%2,%3};\n"
        : "+f"(c[0]), "+f"(c[1]), "+f"(c[2]), "+f"(c[3])
        : "r"(a[0]), "r"(a[1]), "r"(a[2]), "r"(a[3]), "r"(b[0]), "r"(b[1]));
}
__device__ __forceinline__ void ldsm4h(unsigned* r, const __half* p)
{
    unsigned a = (unsigned)__cvta_generic_to_shared(p);
    asm volatile("ldmatrix.sync.aligned.m8n8.x4.shared.b16 {%0,%1,%2,%3}, [%4];\n"
        : "=r"(r[0]), "=r"(r[1]), "=r"(r[2]), "=r"(r[3]) : "r"(a));
}
__device__ __forceinline__ void ldsm2h(unsigned* r, const __half* p)
{
    unsigned a = (unsigned)__cvta_generic_to_shared(p);
    asm volatile("ldmatrix.sync.aligned.m8n8.x2.shared.b16 {%0,%1}, [%2];\n"
        : "=r"(r[0]), "=r"(r[1]) : "r"(a));
}
__device__ __forceinline__ void ldsm2ht(unsigned* r, const __half* p)
{
    unsigned a = (unsigned)__cvta_generic_to_shared(p);
    asm volatile("ldmatrix.sync.aligned.m8n8.x2.trans.shared.b16 {%0,%1}, [%2];\n"
        : "=r"(r[0]), "=r"(r[1]) : "r"(a));
}
__device__ __forceinline__ unsigned pack_h2(float x, float y)
{
    __half2 h = __floats2half2_rn(x, y);
    return *(unsigned*)&h;
}

#define CP16(dst, src) \
    asm volatile("cp.async.cg.shared.global [%0], [%1], 16;\n" :: "r"(dst), "l"(src))
#define CP_COMMIT() asm volatile("cp.async.commit_group;\n")
#define CP_WAIT0()  asm volatile("cp.async.wait_group 0;\n")
#define CP_WAIT1()  asm volatile("cp.async.wait_group 1;\n")

// --------------------------------- weight prep: fp16 round + transpose -----
__global__ void prep_weights_kernel(const float* __restrict__ qs, const float* __restrict__ ps,
                                    const float* __restrict__ f1s, const float* __restrict__ f2s,
                                    const float* __restrict__ qn, const float* __restrict__ pn,
                                    const float* __restrict__ f1n, const float* __restrict__ f2n)
{
    int i = blockIdx.x*256 + threadIdx.x;
    if (i >= 921600) return;
    int j = i;
    const float* src; int N, segbase;
    if (j < 460800) {
        if      (j < 230400) { src = qs;  N = 480; segbase = 0; }
        else if (j < 307200) { src = ps;  N = 160; segbase = 230400; j -= 230400; }
        else if (j < 384000) { src = f1s; N = 160; segbase = 307200; j -= 307200; }
        else                 { src = f2s; N = 160; segbase = 384000; j -= 384000; }
    } else {
        j -= 460800;
        if      (j < 230400) { src = qn;  N = 480; segbase = 460800; }
        else if (j < 307200) { src = pn;  N = 160; segbase = 691200; j -= 230400; }
        else if (j < 384000) { src = f1n; N = 160; segbase = 768000; j -= 307200; }
        else                 { src = f2n; N = 160; segbase = 844800; j -= 384000; }
    }
    int lsz = 160*N;
    int l2 = j / lsz, rem = j - l2*lsz;
    int k = rem / N, n = rem - k*N;
    g_wh[segbase + l2*lsz + n*160 + k] = __float2half_rn(src[j]);
}

// --------------------------------------------------- embed + fused LN ------
__global__ void embed_kernel(const float* __restrict__ x, const int* __restrict__ te,
                             const int* __restrict__ reo_all,
                             const float* __restrict__ node_emb,
                             const float* __restrict__ tod_emb,
                             const float* __restrict__ dow_emb,
                             const float* __restrict__ in_w,
                             const float* __restrict__ in_b)
{
    int j = blockIdx.x, b = blockIdx.y, o = threadIdx.x;
    int lane = o & 31, wid = o >> 5;
    __shared__ float x1[12][3];
    __shared__ float red[5];
    int n = reo_all[j];
    if (o < 12) {
        int p = o;
        size_t base = ((size_t)(b*12 + p))*NNODE + n;
        x1[p][0] = x[base];
        x1[p][1] = (float)te[base*2 + 0] * (1.0f/288.0f);
        x1[p][2] = (float)te[base*2 + 1] * (1.0f/7.0f);
    }
    __syncthreads();
    float v;
    size_t tb = (((size_t)(b*12 + 11))*NNODE + n)*2;
    if (o < 64) {
        v = in_b[o];
        #pragma unroll
        for (int c = 0; c < 3; c++)
            #pragma unroll
            for (int p = 0; p < 12; p++)
                v += x1[p][c] * in_w[(c*12 + p)*64 + o];
    } else if (o < 96) {
        v = tod_emb[te[tb + 0]*32 + (o - 64)];
    } else if (o < 128) {
        v = dow_emb[te[tb + 1]*32 + (o - 96)];
    } else {
        v = node_emb[(size_t)n*32 + (o - 128)];
    }
    float s = v;
    #pragma unroll
    for (int m = 16; m; m >>= 1) s += __shfl_xor_sync(0xffffffffu, s, m);
    if (lane == 0) red[wid] = s;
    __syncthreads();
    float mean = (red[0] + red[1] + red[2] + red[3] + red[4]) * (1.0f/160.0f);
    float d = v - mean;
    float q = d*d;
    #pragma unroll
    for (int m = 16; m; m >>= 1) q += __shfl_xor_sync(0xffffffffu, q, m);
    __syncthreads();
    if (lane == 0) red[wid] = q;
    __syncthreads();
    float w = rsqrtf((red[0] + red[1] + red[2] + red[3] + red[4]) * (1.0f/160.0f) + 1e-6f);
    size_t row = ((size_t)b*NNODE + j)*DD + o;
    g_rex[row] = v;
    g_ln[row] = __float2half_rn(d*w);
}

// ------------------------------------------------------------------ gemm ----
// A: fp16 [row][k]. Wt: fp16 [n][k] stride 160. 3-stage cp.async pipeline.
// OP: 1 = bias+residual -> fp32 C (+opt fused LN -> fp16); 3 = bias -> fp16
template<int OP, int LNOUT>
__global__ void __launch_bounds__(256, 2) gemm_mma_kernel(
    const __half* __restrict__ A, const __half* __restrict__ Wt,
    const float* __restrict__ bias, const float* __restrict__ Rsd,
    float* __restrict__ Cf, __half* __restrict__ Ch,
    __half* __restrict__ LnOut, int ldc)
{
    extern __shared__ char smraw[];
    __half* As = (__half*)smraw;       // [3][128][40]
    __half* Bs = As + 3*128*40;        // [3][160][40]
    float*  S  = (float*)smraw;        // [128][164] (epilogue reuse, LNOUT)
    const int tid = threadIdx.x, lane = tid & 31, wid = tid >> 5;
    const int warp_m = wid >> 2, warp_n = wid & 3;
    const int row0 = blockIdx.x*128, colbase = blockIdx.y*160;

    const int lrow = (lane & 7) + ((lane >> 3) & 1)*8;
    const int lkof = ((lane >> 4) & 1)*8;

    unsigned sAs = (unsigned)__cvta_generic_to_shared(As);
    unsigned sBs = (unsigned)__cvta_generic_to_shared(Bs);

    float acc[4][5][4] = {};

    auto load_tile = [&](int k0, int buf) {
        const __half* Ab = A + (size_t)row0*DD + k0;
        #pragma unroll
        for (int i = 0; i < 2; i++) {
            int idx = tid + i*256; int r = idx >> 2, c = idx & 3;
            CP16(sAs + (unsigned)((buf*128*40 + r*40 + c*8)*2),
                 Ab + (size_t)r*DD + c*8);
        }
        const __half* Wb = Wt + (size_t)colbase*160 + k0;
        #pragma unroll
        for (int i = 0; i < 3; i++) {
            int idx = tid + i*256;
            if (idx < 640) {
                int n = idx >> 2, c = idx & 3;
                CP16(sBs + (unsigned)((buf*160*40 + n*40 + c*8)*2),
                     Wb + (size_t)n*160 + c*8);
            }
        }
    };

    load_tile(0, 0);  CP_COMMIT();
    load_tile(32, 1); CP_COMMIT();

    for (int t = 0; t < 5; t++) {
        if (t < 4) CP_WAIT1(); else CP_WAIT0();
        __syncthreads();
        if (t < 3) { load_tile((t + 2)*32, (t + 2)%3); CP_COMMIT(); }
        int bsel = t % 3;
        const __half* Ab = As + bsel*128*40;
        const __half* Bb = Bs + bsel*160*40;
        #pragma unroll
        for (int ks = 0; ks < 2; ks++) {
            unsigned af[4][4], bf[5][2];
            #pragma unroll
            for (int i = 0; i < 4; i++)
                ldsm4h(af[i], Ab + (warp_m*64 + i*16 + lrow)*40 + ks*16 + lkof);
            #pragma unroll
            for (int j = 0; j < 5; j++)
                ldsm2h(bf[j], Bb + (warp_n*40 + j*8 + (lane & 7))*40
                              + ks*16 + ((lane >> 3) & 1)*8);
            #pragma unroll
            for (int i = 0; i < 4; i++)
                #pragma unroll
                for (int j = 0; j < 5; j++)
                    mma16(acc[i][j], af[i], bf[j]);
        }
    }

    if (LNOUT) __syncthreads();

    int rwl = warp_m*64 + (lane >> 2);
    int cwl = warp_n*40 + 2*(lane & 3);
    #pragma unroll
    for (int j = 0; j < 5; j++) {
        int cl = cwl + j*8, c = colbase + cl;
        float b0 = bias[c], b1 = bias[c + 1];
        #pragma unroll
        for (int i = 0; i < 4; i++) {
            #pragma unroll
            for (int h = 0; h < 2; h++) {
                int rl = rwl + i*16 + h*8, r = row0 + rl;
                float v0 = acc[i][j][2*h + 0] + b0;
                float v1 = acc[i][j][2*h + 1] + b1;
                if (OP == 1) {
                    float2 rs = *(const float2*)(Rsd + (size_t)r*ldc + c);
                    v0 += rs.x; v1 += rs.y;
                    *(float2*)(Cf + (size_t)r*ldc + c) = make_float2(v0, v1);
                    if (LNOUT) { S[rl*164 + cl] = v0; S[rl*164 + cl + 1] = v1; }
                }
                if (OP == 3)
                    *(__half2*)(Ch + (size_t)r*ldc + c) = __floats2half2_rn(v0, v1);
            }
        }
    }

    if (LNOUT) {
        __syncthreads();
        #pragma unroll 1
        for (int rr = 0; rr < 16; rr++) {
            int rl = wid*16 + rr;
            float vv[5]; float s = 0.f;
            #pragma unroll
            for (int q = 0; q < 5; q++) { vv[q] = S[rl*164 + lane + 32*q]; s += vv[q]; }
            #pragma unroll
            for (int m = 16; m; m >>= 1) s += __shfl_xor_sync(0xffffffffu, s, m);
            float mean = s * (1.0f/160.0f);
            float qv = 0.f;
            #pragma unroll
            for (int q = 0; q < 5; q++) { float d = vv[q]-mean; qv += d*d; }
            #pragma unroll
            for (int m = 16; m; m >>= 1) qv += __shfl_xor_sync(0xffffffffu, qv, m);
            float w = rsqrtf(qv * (1.0f/160.0f) + 1e-6f);
            __half* yr = LnOut + (size_t)(row0 + rl)*DD;
            #pragma unroll
            for (int q = 0; q < 5; q++)
                yr[lane + 32*q] = __float2half_rn((vv[q]-mean)*w);
        }
    }
}

// ------------------------------------------------------------- fused MLP ----
template<int LNOUT>
__global__ void __launch_bounds__(256, 2) mlp_mma_kernel(
    const __half* __restrict__ A, const __half* __restrict__ W1,
    const float* __restrict__ b1, const __half* __restrict__ W2,
    const float* __restrict__ b2, const float* __restrict__ Rsd,
    float* __restrict__ Cf, __half* __restrict__ LnOut)
{
    extern __shared__ char smraw[];
    __half* As = (__half*)smraw;       // [3][128][40]
    __half* Bs = As + 3*128*40;        // [3][160][40]
    __half* Hs = Bs + 3*160*40;        // [128][168]
    float*  S  = (float*)smraw;        // [128][164] (epilogue reuse, LNOUT)
    const int tid = threadIdx.x, lane = tid & 31, wid = tid >> 5;
    const int warp_m = wid >> 2, warp_n = wid & 3;
    const int row0 = blockIdx.x*128;

    const int lrow = (lane & 7) + ((lane >> 3) & 1)*8;
    const int lkof = ((lane >> 4) & 1)*8;

    unsigned sAs = (unsigned)__cvta_generic_to_shared(As);
    unsigned sBs = (unsigned)__cvta_generic_to_shared(Bs);

    float acc[4][5][4] = {};

    auto load_tile = [&](int k0, int buf) {
        const __half* Ab = A + (size_t)row0*DD + k0;
        #pragma unroll
        for (int i = 0; i < 2; i++) {
            int idx = tid + i*256; int r = idx >> 2, c = idx & 3;
            CP16(sAs + (unsigned)((buf*128*40 + r*40 + c*8)*2),
                 Ab + (size_t)r*DD + c*8);
        }
        const __half* Wb = W1 + k0;
        #pragma unroll
        for (int i = 0; i < 3; i++) {
            int idx = tid + i*256;
            if (idx < 640) {
                int n = idx >> 2, c = idx & 3;
                CP16(sBs + (unsigned)((buf*160*40 + n*40 + c*8)*2),
                     Wb + (size_t)n*160 + c*8);
            }
        }
    };
    auto load_w2 = [&](int k0, int buf) {
        const __half* Wb = W2 + k0;
        #pragma unroll
        for (int i = 0; i < 3; i++) {
            int idx = tid + i*256;
            if (idx < 640) {
                int n = idx >> 2, c = idx & 3;
                CP16(sBs + (unsigned)((buf*160*40 + n*40 + c*8)*2),
                     Wb + (size_t)n*160 + c*8);
            }
        }
    };

    // pass 1 : H = gelu(A@W1 + b1)
    load_tile(0, 0);  CP_COMMIT();
    load_tile(32, 1); CP_COMMIT();
    for (int t = 0; t < 5; t++) {
        if (t < 4) CP_WAIT1(); else CP_WAIT0();
        __syncthreads();
        if (t < 3) { load_tile((t + 2)*32, (t + 2)%3); CP_COMMIT(); }
        int bsel = t % 3;
        const __half* Ab = As + bsel*128*40;
        const __half* Bb = Bs + bsel*160*40;
        #pragma unroll
        for (int ks = 0; ks < 2; ks++) {
            unsigned af[4][4], bf[5][2];
            #pragma unroll
            for (int i = 0; i < 4; i++)
                ldsm4h(af[i], Ab + (warp_m*64 + i*16 + lrow)*40 + ks*16 + lkof);
            #pragma unroll
            for (int j = 0; j < 5; j++)
                ldsm2h(bf[j], Bb + (warp_n*40 + j*8 + (lane & 7))*40
                              + ks*16 + ((lane >> 3) & 1)*8);
            #pragma unroll
            for (int i = 0; i < 4; i++)
                #pragma unroll
                for (int j = 0; j < 5; j++)
                    mma16(acc[i][j], af[i], bf[j]);
        }
    }
    __syncthreads();

    const int rwl = warp_m*64 + (lane >> 2);
    const int cwl = warp_n*40 + 2*(lane & 3);
    #pragma unroll
    for (int j = 0; j < 5; j++) {
        int cl = cwl + j*8;
        float b0 = b1[cl], b1v = b1[cl + 1];
        #pragma unroll
        for (int i = 0; i < 4; i++) {
            #pragma unroll
            for (int h = 0; h < 2; h++) {
                int rl = rwl + i*16 + h*8;
                float v0 = acc[i][j][2*h + 0] + b0;
                float v1 = acc[i][j][2*h + 1] + b1v;
                v0 = 0.5f*v0*(1.0f + erff(v0*0.70710678118654752f));
                v1 = 0.5f*v1*(1.0f + erff(v1*0.70710678118654752f));
                *(__half2*)(Hs + rl*168 + cl) = __floats2half2_rn(v0, v1);
                acc[i][j][2*h] = 0.f; acc[i][j][2*h + 1] = 0.f;
            }
        }
    }
    __syncthreads();

    // pass 2 : C = H@W2 + b2 + Rsd
    load_w2(0, 0);  CP_COMMIT();
    load_w2(32, 1); CP_COMMIT();
    for (int t = 0; t < 5; t++) {
        if (t < 4) CP_WAIT1(); else CP_WAIT0();
        __syncthreads();
        if (t < 3) { load_w2((t + 2)*32, (t + 2)%3); CP_COMMIT(); }
        int bsel = t % 3;
        const __half* Bb = Bs + bsel*160*40;
        #pragma unroll
        for (int ks = 0; ks < 2; ks++) {
            unsigned af[4][4], bf[5][2];
            #pragma unroll
            for (int i = 0; i < 4; i++)
                ldsm4h(af[i], Hs + (warp_m*64 + i*16 + lrow)*168
                              + t*32 + ks*16 + lkof);
            #pragma unroll
            for (int j = 0; j < 5; j++)
                ldsm2h(bf[j], Bb + (warp_n*40 + j*8 + (lane & 7))*40
                              + ks*16 + ((lane >> 3) & 1)*8);
            #pragma unroll
            for (int i = 0; i < 4; i++)
                #pragma unroll
                for (int j = 0; j < 5; j++)
                    mma16(acc[i][j], af[i], bf[j]);
        }
    }
    __syncthreads();

    #pragma unroll
    for (int j = 0; j < 5; j++) {
        int cl = cwl + j*8;
        float b0 = b2[cl], b1v = b2[cl + 1];
        #pragma unroll
        for (int i = 0; i < 4; i++) {
            #pragma unroll
            for (int h = 0; h < 2; h++) {
                int rl = rwl + i*16 + h*8, r = row0 + rl;
                float2 rs = *(const float2*)(Rsd + (size_t)r*DD + cl);
                float v0 = acc[i][j][2*h + 0] + b0 + rs.x;
                float v1 = acc[i][j][2*h + 1] + b1v + rs.y;
                *(float2*)(Cf + (size_t)r*DD + cl) = make_float2(v0, v1);
                if (LNOUT) { S[rl*164 + cl] = v0; S[rl*164 + cl + 1] = v1; }
            }
        }
    }

    if (LNOUT) {
        __syncthreads();
        #pragma unroll 1
        for (int rr = 0; rr < 16; rr++) {
            int rl = wid*16 + rr;
            float vv[5]; float s = 0.f;
            #pragma unroll
            for (int q = 0; q < 5; q++) { vv[q] = S[rl*164 + lane + 32*q]; s += vv[q]; }
            #pragma unroll
            for (int m = 16; m; m >>= 1) s += __shfl_xor_sync(0xffffffffu, s, m);
            float mean = s * (1.0f/160.0f);
            float qv = 0.f;
            #pragma unroll
            for (int q = 0; q < 5; q++) { float d = vv[q]-mean; qv += d*d; }
            #pragma unroll
            for (int m = 16; m; m >>= 1) qv += __shfl_xor_sync(0xffffffffu, qv, m);
            float w = rsqrtf(qv * (1.0f/160.0f) + 1e-6f);
            __half* yr = LnOut + (size_t)(row0 + rl)*DD;
            #pragma unroll
            for (int q = 0; q < 5; q++)
                yr[lane + 32*q] = __float2half_rn((vv[q]-mean)*w);
        }
    }
}

// ------------------------------------------------------ spatial attention ----
__global__ void __launch_bounds__(128) spat_attn_kernel(const __half* __restrict__ qkv,
                                                        __half* __restrict__ out)
{
    extern __shared__ __half G[];          // [4][16][488]
    const int tid = threadIdx.x, lane = tid & 31, w = tid >> 5;
    const int gbase = blockIdx.x*4;
    unsigned sG = (unsigned)__cvta_generic_to_shared(G);

    #pragma unroll
    for (int i = 0; i < 30; i++) {
        int idx = tid + i*128;
        int grp = idx/960, rem = idx - grp*960;
        int row = rem/60, c = rem - row*60;
        CP16(sG + (unsigned)(((grp*16 + row)*488 + c*8)*2),
             qkv + ((size_t)(gbase + grp)*16 + row)*QW + c*8);
    }
    CP_COMMIT(); CP_WAIT0();
    __syncthreads();

    const __half* Gm = G + w*16*488;
    const int lrow = (lane & 7) + ((lane >> 3) & 1)*8;
    const int lkof = ((lane >> 4) & 1)*8;
    const float scale = 0.07905694150420949f;

    float sv0[4] = {}, sv1[4] = {};
    #pragma unroll
    for (int ks = 0; ks < 10; ks++) {
        unsigned af[4], bf0[2], bf1[2];
        ldsm4h(af, Gm + lrow*488 + ks*16 + lkof);
        ldsm2h(bf0, Gm + ((lane & 7)    )*488 + 160 + ks*16 + ((lane >> 3) & 1)*8);
        ldsm2h(bf1, Gm + ((lane & 7) + 8)*488 + 160 + ks*16 + ((lane >> 3) & 1)*8);
        mma16(sv0, af, bf0);
        mma16(sv1, af, bf1);
    }

    float st[4] = {sv0[0]*scale, sv0[1]*scale, sv1[0]*scale, sv1[1]*scale};
    float sb[4] = {sv0[2]*scale, sv0[3]*scale, sv1[2]*scale, sv1[3]*scale};
    float mt = fmaxf(fmaxf(st[0], st[1]), fmaxf(st[2], st[3]));
    float mb = fmaxf(fmaxf(sb[0], sb[1]), fmaxf(sb[2], sb[3]));
    mt = fmaxf(mt, __shfl_xor_sync(0xffffffffu, mt, 1));
    mt = fmaxf(mt, __shfl_xor_sync(0xffffffffu, mt, 2));
    mb = fmaxf(mb, __shfl_xor_sync(0xffffffffu, mb, 1));
    mb = fmaxf(mb, __shfl_xor_sync(0xffffffffu, mb, 2));
    float pt[4], pb[4], sumt = 0.f, sumb = 0.f;
    #pragma unroll
    for (int q = 0; q < 4; q++) {
        pt[q] = expf(st[q] - mt); sumt += pt[q];
        pb[q] = expf(sb[q] - mb); sumb += pb[q];
    }
    sumt += __shfl_xor_sync(0xffffffffu, sumt, 1);
    sumt += __shfl_xor_sync(0xffffffffu, sumt, 2);
    sumb += __shfl_xor_sync(0xffffffffu, sumb, 1);
    sumb += __shfl_xor_sync(0xffffffffu, sumb, 2);
    float it = 1.0f/sumt, ib = 1.0f/sumb;

    unsigned pa[4];
    pa[0] = pack_h2(pt[0]*it, pt[1]*it);
    pa[1] = pack_h2(pb[0]*ib, pb[1]*ib);
    pa[2] = pack_h2(pt[2]*it, pt[3]*it);
    pa[3] = pack_h2(pb[2]*ib, pb[3]*ib);

    int r = lane >> 2, c2 = 2*(lane & 3);
    size_t orow_t = ((size_t)(gbase + w)*16 + r    )*DD;
    size_t orow_b = ((size_t)(gbase + w)*16 + r + 8)*DD;
    #pragma unroll
    for (int j = 0; j < 20; j++) {
        unsigned bf[2];
        ldsm2ht(bf, Gm + ((lane & 7) + ((lane >> 3) & 1)*8)*488 + 320 + j*8);
        float o4[4] = {};
        mma16(o4, pa, bf);
        *(__half2*)(out + orow_t + j*8 + c2) = __floats2half2_rn(o4[0], o4[1]);
        *(__half2*)(out + orow_b + j*8 + c2) = __floats2half2_rn(o4[2], o4[3]);
    }
}

// --------------------------------------------------------- node attention ----
__global__ void __launch_bounds__(256, 2) node_attn_kernel(const __half* __restrict__ qkv,
                                                           __half* __restrict__ out)
{
    extern __shared__ char smraw[];
    __half* Qs   = (__half*)smraw;          // [64][168]
    __half* Ks   = Qs + 64*168;             // [2][64][168]
    __half* Vs   = Ks + 2*64*168;           // [64][168]
    __half* Ps16 = Vs + 64*168;             // [64][72]
    float*  l_s  = (float*)(Ps16 + 64*72);  // [64]

    const int qt = blockIdx.x, g = blockIdx.y;
    const int b = g >> 4, s = g & 15;
    const int tid = threadIdx.x, lane = tid & 31, w = tid >> 5;
    const int wm = w >> 2, wn = w & 3;
    const int ar = wm*32 + (lane >> 2);
    const int lrow = (lane & 7) + ((lane >> 3) & 1)*8;
    const int lkof = ((lane >> 4) & 1)*8;
    const size_t rowstride = (size_t)PSZ*QW;
    const __half* base = qkv + (size_t)b*NNODE*QW + (size_t)s*QW;
    const float scale = 0.07905694150420949f;

    unsigned sQ = (unsigned)__cvta_generic_to_shared(Qs);
    unsigned sK = (unsigned)__cvta_generic_to_shared(Ks);
    unsigned sV = (unsigned)__cvta_generic_to_shared(Vs);

    if (tid < 64) l_s[tid] = 0.f;

    auto ldK = [&](int kt, int buf) {
        #pragma unroll
        for (int i = 0; i < 5; i++) {
            int idx = tid + i*256; int r = idx/20, c = idx%20;
            CP16(sK + (unsigned)((buf*64*168 + r*168 + c*8)*2),
                 base + (size_t)(kt*64 + r)*rowstride + 160 + c*8);
        }
    };
    auto ldV = [&](int kt) {
        #pragma unroll
        for (int i = 0; i < 5; i++) {
            int idx = tid + i*256; int r = idx/20, c = idx%20;
            CP16(sV + (unsigned)((r*168 + c*8)*2),
                 base + (size_t)(kt*64 + r)*rowstride + 320 + c*8);
        }
    };
    #pragma unroll
    for (int i = 0; i < 5; i++) {
        int idx = tid + i*256; int r = idx/20, c = idx%20;
        CP16(sQ + (unsigned)((r*168 + c*8)*2),
             base + (size_t)(qt*64 + r)*rowstride + c*8);
    }
    ldK(0, 0);
    CP_COMMIT();

    float o[2][5][4] = {};

    for (int kt = 0; kt < 8; kt++) {
        CP_WAIT0();
        __syncthreads();
        ldV(kt); CP_COMMIT();
        if (kt < 7) ldK(kt + 1, (kt + 1) & 1);
        CP_COMMIT();
        const __half* Kb = Ks + (kt & 1)*64*168;

        float sv[2][2][4] = {};
        #pragma unroll
        for (int ks = 0; ks < 10; ks++) {
            unsigned af0[4], af1[4], bf0[2], bf1[2];
            ldsm4h(af0, Qs + (wm*32      + lrow)*168 + ks*16 + lkof);
            ldsm4h(af1, Qs + (wm*32 + 16 + lrow)*168 + ks*16 + lkof);
            ldsm2h(bf0, Kb + (wn*16     + (lane & 7))*168 + ks*16 + ((lane >> 3) & 1)*8);
            ldsm2h(bf1, Kb + (wn*16 + 8 + (lane & 7))*168 + ks*16 + ((lane >> 3) & 1)*8);
            mma16(sv[0][0], af0, bf0); mma16(sv[0][1], af0, bf1);
            mma16(sv[1][0], af1, bf0); mma16(sv[1][1], af1, bf1);
        }

        #pragma unroll
        for (int i = 0; i < 2; i++) {
            int r0 = ar + 16*i;
            float e[2][4];
            #pragma unroll
            for (int j = 0; j < 2; j++)
                #pragma unroll
                for (int q = 0; q < 4; q++)
                    e[j][q] = __expf(sv[i][j][q]*scale);
            #pragma unroll
            for (int j = 0; j < 2; j++) {
                int c0 = wn*16 + 8*j + 2*(lane & 3);
                *(__half2*)&Ps16[(r0    )*72 + c0] = __floats2half2_rn(e[j][0], e[j][1]);
                *(__half2*)&Ps16[(r0 + 8)*72 + c0] = __floats2half2_rn(e[j][2], e[j][3]);
            }
            float rs0 = e[0][0] + e[0][1] + e[1][0] + e[1][1];
            float rs8 = e[0][2] + e[0][3] + e[1][2] + e[1][3];
            rs0 += __shfl_xor_sync(0xffffffffu, rs0, 1);
            rs0 += __shfl_xor_sync(0xffffffffu, rs0, 2);
            rs8 += __shfl_xor_sync(0xffffffffu, rs8, 1);
            rs8 += __shfl_xor_sync(0xffffffffu, rs8, 2);
            if ((lane & 3) == 0) {
                atomicAdd(&l_s[r0], rs0);
                atomicAdd(&l_s[r0 + 8], rs8);
            }
        }
        __syncthreads();

        CP_WAIT1();

        #pragma unroll
        for (int ks = 0; ks < 4; ks++) {
            unsigned af0[4], af1[4], bf[5][2];
            ldsm4h(af0, Ps16 + (wm*32      + lrow)*72 + ks*16 + lkof);
            ldsm4h(af1, Ps16 + (wm*32 + 16 + lrow)*72 + ks*16 + lkof);
            #pragma unroll
            for (int j = 0; j < 5; j++)
                ldsm2ht(bf[j], Vs + (ks*16 + (lane & 7) + ((lane >> 3) & 1)*8)*168
                               + wn*40 + j*8);
            #pragma unroll
            for (int j = 0; j < 5; j++) { mma16(o[0][j], af0, bf[j]); mma16(o[1][j], af1, bf[j]); }
        }
    }

    __syncthreads();
    #pragma unroll
    for (int i = 0; i < 2; i++)
        #pragma unroll
        for (int h = 0; h < 2; h++) {
            int rl = ar + 16*i + 8*h;
            float inv = 1.0f / l_s[rl];
            size_t orow = ((size_t)b*NNODE + (size_t)(qt*64 + rl)*PSZ + s)*DD;
            #pragma unroll
            for (int j = 0; j < 5; j++) {
                int c = wn*40 + j*8 + 2*(lane & 3);
                *(__half2*)(out + orow + c) =
                    __floats2half2_rn(o[i][j][2*h]*inv, o[i][j][2*h + 1]*inv);
            }
        }
}

// --------------------------------------------- inverse map + regression ----
__global__ void map_init_kernel()
{
    g_map[blockIdx.x*256 + threadIdx.x] = -1;
}

__global__ void map_build_kernel(const int* __restrict__ ori, const int* __restrict__ reo)
{
    int i = blockIdx.x*256 + threadIdx.x;
    g_map[ori[i]] = reo[i];
}

__global__ void __launch_bounds__(256) pred_kernel(const float* __restrict__ rex,
                                                   const float* __restrict__ reg_w,
                                                   const float* __restrict__ reg_b,
                                                   float* __restrict__ out)
{
    __shared__ float T[32][164];
    __shared__ float Wsh[12*160];
    int n0 = blockIdx.x*32, b = blockIdx.y, tid = threadIdx.x;
    for (int t = tid; t < 12*160; t += 256) Wsh[t] = reg_w[t];
    for (int t = tid; t < 32*160; t += 256) {
        int nn = t/160, d = t%160;
        int src = g_map[n0 + nn];
        T[nn][d] = (src >= 0) ? rex[((size_t)b*NNODE + src)*DD + d] : 0.f;
    }
    __syncthreads();
    for (int t = tid; t < 384; t += 256) {
        int o = t/32, nn = t%32;
        float acc = reg_b[o];
        #pragma unroll 8
        for (int d = 0; d < 160; d++) acc += Wsh[o*160 + d]*T[nn][d];
        out[((size_t)(b*12 + o))*NNODE + n0 + nn] = acc;
    }
}

// ---------------------------------------------------------------- launch ----
extern "C" void kernel_launch(void* const* d_in, const int* in_sizes, int n_in,
                              void* d_out, int out_size)
{
    const float* x        = (const float*)d_in[0];
    const int*   te       = (const int*)  d_in[1];
    const int*   reo_all  = (const int*)  d_in[2];
    const int*   ori_p    = (const int*)  d_in[3];
    const int*   reo_p    = (const int*)  d_in[4];
    const float* node_emb = (const float*)d_in[5];
    const float* tod_emb  = (const float*)d_in[6];
    const float* dow_emb  = (const float*)d_in[7];
    const float* in_w     = (const float*)d_in[8];
    const float* in_b     = (const float*)d_in[9];
    const float* qkv_s_w  = (const float*)d_in[10];
    const float* qkv_s_b  = (const float*)d_in[11];
    const float* proj_s_w = (const float*)d_in[12];
    const float* proj_s_b = (const float*)d_in[13];
    const float* fc1_s_w  = (const float*)d_in[14];
    const float* fc1_s_b  = (const float*)d_in[15];
    const float* fc2_s_w  = (const float*)d_in[16];
    const float* fc2_s_b  = (const float*)d_in[17];
    const float* qkv_n_w  = (const float*)d_in[18];
    const float* qkv_n_b  = (const float*)d_in[19];
    const float* proj_n_w = (const float*)d_in[20];
    const float* proj_n_b = (const float*)d_in[21];
    const float* fc1_n_w  = (const float*)d_in[22];
    const float* fc1_n_b  = (const float*)d_in[23];
    const float* fc2_n_w  = (const float*)d_in[24];
    const float* fc2_n_b  = (const float*)d_in[25];
    const float* reg_w    = (const float*)d_in[26];
    const float* reg_b    = (const float*)d_in[27];
    float* out = (float*)d_out;

    int B = in_sizes[0] / (12*NNODE);
    int M = B*NNODE;

    float *rex;
    __half *ln, *tmp, *qkv, *wh;
    cudaGetSymbolAddress((void**)&rex,  g_rex);
    cudaGetSymbolAddress((void**)&ln,   g_ln);
    cudaGetSymbolAddress((void**)&tmp,  g_tmp);
    cudaGetSymbolAddress((void**)&qkv,  g_qkv);
    cudaGetSymbolAddress((void**)&wh,   g_wh);

    const int GEMM_SMEM = 128*164*4;                                   // 83968
    const int MLP_SMEM  = (3*128*40 + 3*160*40 + 128*168)*2;           // 112128
    const int ATTN_SMEM = (64*168*4)*2 + 64*72*2 + 64*4;               // 95488
    const int SPAT_SMEM = 4*16*488*2;                                  // 62464
    cudaFuncSetAttribute(gemm_mma_kernel<1,1>, cudaFuncAttributeMaxDynamicSharedMemorySize, GEMM_SMEM);
    cudaFuncSetAttribute(gemm_mma_kernel<1,0>, cudaFuncAttributeMaxDynamicSharedMemorySize, GEMM_SMEM);
    cudaFuncSetAttribute(gemm_mma_kernel<3,0>, cudaFuncAttributeMaxDynamicSharedMemorySize, GEMM_SMEM);
    cudaFuncSetAttribute(mlp_mma_kernel<1>,    cudaFuncAttributeMaxDynamicSharedMemorySize, MLP_SMEM);
    cudaFuncSetAttribute(mlp_mma_kernel<0>,    cudaFuncAttributeMaxDynamicSharedMemorySize, MLP_SMEM);
    cudaFuncSetAttribute(node_attn_kernel,     cudaFuncAttributeMaxDynamicSharedMemorySize, ATTN_SMEM);
    cudaFuncSetAttribute(spat_attn_kernel,     cudaFuncAttributeMaxDynamicSharedMemorySize, SPAT_SMEM);

    prep_weights_kernel<<<3600, 256>>>(qkv_s_w, proj_s_w, fc1_s_w, fc2_s_w,
                                       qkv_n_w, proj_n_w, fc1_n_w, fc2_n_w);
    map_init_kernel<<<NNODE/256, 256>>>();
    map_build_kernel<<<NNODE/256, 256>>>(ori_p, reo_p);

    embed_kernel<<<dim3(NNODE, B), DD>>>(x, te, reo_all, node_emb, tod_emb, dow_emb,
                                         in_w, in_b);

    for (int l = 0; l < 3; l++) {
        const __half* Wq_s = wh + 0      + (size_t)l*76800;
        const __half* Wp_s = wh + 230400 + (size_t)l*25600;
        const __half* W1_s = wh + 307200 + (size_t)l*25600;
        const __half* W2_s = wh + 384000 + (size_t)l*25600;
        const __half* Wq_n = wh + 460800 + (size_t)l*76800;
        const __half* Wp_n = wh + 691200 + (size_t)l*25600;
        const __half* W1_n = wh + 768000 + (size_t)l*25600;
        const __half* W2_n = wh + 844800 + (size_t)l*25600;
        size_t ob3 = (size_t)l*QW, ob1 = (size_t)l*DD;

        // --- spatial attention block ---
        gemm_mma_kernel<3,0><<<dim3(M/128, 3), 256, GEMM_SMEM>>>(ln, Wq_s, qkv_s_b + ob3,
                                                nullptr, nullptr, qkv, nullptr, QW);
        spat_attn_kernel<<<M/64, 128, SPAT_SMEM>>>(qkv, tmp);
        gemm_mma_kernel<1,1><<<dim3(M/128, 1), 256, GEMM_SMEM>>>(tmp, Wp_s, proj_s_b + ob1,
                                                rex, rex, nullptr, ln, DD);
        // --- spatial MLP (fused) ---
        mlp_mma_kernel<1><<<M/128, 256, MLP_SMEM>>>(ln, W1_s, fc1_s_b + ob1,
                                                W2_s, fc2_s_b + ob1, rex, rex, ln);
        // --- node attention block ---
        gemm_mma_kernel<3,0><<<dim3(M/128, 3), 256, GEMM_SMEM>>>(ln, Wq_n, qkv_n_b + ob3,
                                                nullptr, nullptr, qkv, nullptr, QW);
        node_attn_kernel<<<dim3(PNUM/64, B*PSZ), 256, ATTN_SMEM>>>(qkv, tmp);
        gemm_mma_kernel<1,1><<<dim3(M/128, 1), 256, GEMM_SMEM>>>(tmp, Wp_n, proj_n_b + ob1,
                                                rex, rex, nullptr, ln, DD);
        // --- node MLP (fused) ---
        if (l < 2)
            mlp_mma_kernel<1><<<M/128, 256, MLP_SMEM>>>(ln, W1_n, fc1_n_b + ob1,
                                                W2_n, fc2_n_b + ob1, rex, rex, ln);
        else
            mlp_mma_kernel<0><<<M/128, 256, MLP_SMEM>>>(ln, W1_n, fc1_n_b + ob1,
                                                W2_n, fc2_n_b + ob1, rex, rex, nullptr);
    }

    pred_kernel<<<dim3(NNODE/32, B), 256>>>(rex, reg_w, reg_b, out);
}